// round 1
// baseline (speedup 1.0000x reference)
#include <cuda_runtime.h>

#define NBATCH 16
#define NF     128
#define NT     4096
#define NS     4
#define TPB    256
#define PT     16   // elements per thread: TPB*PT == NT

__device__ __forceinline__ float fast_exp2(float x) {
    float r;
    asm("ex2.approx.ftz.f32 %0, %1;" : "=f"(r) : "f"(x));
    return r;
}
__device__ __forceinline__ float fast_log2(float x) {
    float r;
    asm("lg2.approx.ftz.f32 %0, %1;" : "=f"(r) : "f"(x));
    return r;
}

__global__ __launch_bounds__(TPB)
void mrpcen_kernel(const float* __restrict__ x,
                   const float* __restrict__ alpha_log,
                   const float* __restrict__ delta_log,
                   const float* __restrict__ r_log,
                   float* __restrict__ out)
{
    const int row = blockIdx.x;          // b*NF + f
    const int f   = row & (NF - 1);
    const int b   = row >> 7;
    const int tid = threadIdx.x;

    // s values are compile-time-fixed by the problem (T_VALUES * 44100/512),
    // computed in fp32 to mirror the reference pipeline.
    float s[NS], a[NS], A16[NS];
    {
        const float tv[NS] = {0.015f, 0.06f, 0.25f, 1.0f};
#pragma unroll
        for (int i = 0; i < NS; i++) {
            float tt = tv[i] * (44100.0f / 512.0f);
            float d2 = 2.0f * tt * tt;
            s[i] = (sqrtf(1.0f + 2.0f * d2) - 1.0f) / d2;
            a[i] = 1.0f - s[i];
            float a2 = a[i] * a[i], a4 = a2 * a2, a8 = a4 * a4;
            A16[i] = a8 * a8;
        }
    }

    const float al    = alpha_log[f];
    const float dl    = delta_log[f];
    const float rl    = r_log[f];
    const float alpha = __expf(al);
    const float delta = __expf(dl);
    const float rr    = __expf(rl);
    const float delta_r = __expf(rr * dl);   // delta^r = exp(r * delta_log)

    // Load this thread's 16 contiguous x values (held in registers for both passes)
    const float* xrow = x + (size_t)row * NT;
    float xv[PT];
#pragma unroll
    for (int j = 0; j < PT / 4; j++) {
        float4 v = *reinterpret_cast<const float4*>(xrow + tid * PT + j * 4);
        xv[j * 4 + 0] = v.x; xv[j * 4 + 1] = v.y;
        xv[j * 4 + 2] = v.z; xv[j * 4 + 3] = v.w;
    }

    __shared__ float2 sc[NS][TPB];   // (A, B) affine carries per s

    // ---- pass 1: per-thread local recurrence with m_in = 0 -> carry (A, B) ----
#pragma unroll
    for (int si = 0; si < NS; si++) {
        float m = 0.0f;
#pragma unroll
        for (int k = 0; k < PT; k++)
            m = fmaf(a[si], m, s[si] * xv[k]);
        float A = A16[si], Bc = m;
        if (tid == 0) {
            // boundary m[0] = x[0]  <=>  m_in = x[0] (since a + s == 1)
            Bc = fmaf(A, xv[0], Bc);
            A  = 0.0f;
        }
        sc[si][tid] = make_float2(A, Bc);
    }
    __syncthreads();

    // ---- Hillis-Steele inclusive scan of affine carries over 256 threads ----
    for (int d = 1; d < TPB; d <<= 1) {
        float2 v[NS];
        const bool act = (tid >= d);
        if (act) {
#pragma unroll
            for (int si = 0; si < NS; si++) {
                float2 p = sc[si][tid - d];
                float2 c = sc[si][tid];
                // compose: out = Ac*(Ap*m + Bp) + Bc
                v[si] = make_float2(p.x * c.x, fmaf(c.x, p.y, c.y));
            }
        }
        __syncthreads();
        if (act) {
#pragma unroll
            for (int si = 0; si < NS; si++) sc[si][tid] = v[si];
        }
        __syncthreads();
    }

    // ---- pass 2: re-run recurrence with true m_in, fuse PCEN, store ----
    const size_t obase = (((size_t)b * NS) * NF + f) * (size_t)NT + (size_t)tid * PT;
#pragma unroll
    for (int si = 0; si < NS; si++) {
        // tid 0: m_in = x[0] gives m[0] = a*x0 + s*x0 = x0 exactly (a+s=1)
        float m = (tid == 0) ? xv[0] : sc[si][tid - 1].y;
        float* orow = out + obase + (size_t)si * (NF * NT);
#pragma unroll
        for (int j = 0; j < PT / 4; j++) {
            float tmp[4];
#pragma unroll
            for (int q = 0; q < 4; q++) {
                const int k = j * 4 + q;
                m = fmaf(a[si], m, s[si] * xv[k]);
                const float u  = 1e-5f + m;                       // eps + m
                const float sm = fast_exp2(-alpha * fast_log2(u)); // (eps+m)^-alpha
                const float v2 = fmaf(xv[k], sm, delta);           // x*smooth + delta
                tmp[q] = fast_exp2(rr * fast_log2(v2)) - delta_r;  // v^r - delta^r
            }
            float4 o;
            o.x = tmp[0]; o.y = tmp[1]; o.z = tmp[2]; o.w = tmp[3];
            *reinterpret_cast<float4*>(orow + j * 4) = o;
        }
    }
}

extern "C" void kernel_launch(void* const* d_in, const int* in_sizes, int n_in,
                              void* d_out, int out_size) {
    const float* x         = (const float*)d_in[0];
    const float* alpha_log = (const float*)d_in[1];
    const float* delta_log = (const float*)d_in[2];
    const float* r_log     = (const float*)d_in[3];
    float* out             = (float*)d_out;
    (void)in_sizes; (void)n_in; (void)out_size;

    dim3 grid(NBATCH * NF);   // 2048 blocks: one per (b, f) row
    dim3 block(TPB);
    mrpcen_kernel<<<grid, block>>>(x, alpha_log, delta_log, r_log, out);
}